// round 6
// baseline (speedup 1.0000x reference)
#include <cuda_runtime.h>
#include <cstddef>

// Problem constants
#define B_  8
#define N_  1024
#define R_  16384
#define D_  32
#define E_  64
#define H_  512

// ---------------------------------------------------------------------------
// Scratch (device globals; no allocations allowed)
// ---------------------------------------------------------------------------
__device__ float g_node[(size_t)B_ * R_ * 64];   // [B*R, 64] node_obj; reused as h3
__device__ float g_h1 [(size_t)B_ * R_ * H_];    // [B*R, 512]
__device__ float g_h2 [(size_t)B_ * R_ * H_];    // [B*R, 512]
__device__ float g_edge[(size_t)B_ * R_ * E_];   // [B*R, 64]
__device__ float g_agg [(size_t)B_ * N_ * E_];   // [B*N, 64]
__device__ float g_upd [(size_t)B_ * N_ * (D_ + E_)]; // [B*N, 96]
__device__ float g_hn  [(size_t)B_ * N_ * H_];   // [B*N, 512]

// ---------------------------------------------------------------------------
// Gather: node[b*R+r, 0:32] = sum_n obj[b,n,:]*Rs[n,r]
//         node[b*R+r,32:64] = sum_n obj[b,n,:]*Rr[n,r]
// Block: 128 threads, each owns one r; tile n by 32.
// ---------------------------------------------------------------------------
__global__ __launch_bounds__(128)
void gather_kernel(const float* __restrict__ obj,
                   const float* __restrict__ Rs,
                   const float* __restrict__ Rr,
                   float* __restrict__ node)
{
    const int b  = blockIdx.y;
    const int tx = threadIdx.x;
    const int r  = blockIdx.x * 128 + tx;

    __shared__ float sS[32][128];
    __shared__ float sR[32][128];
    __shared__ float sO[32][32];

    float accS[32];
    float accD[32];
#pragma unroll
    for (int d = 0; d < 32; d++) { accS[d] = 0.f; accD[d] = 0.f; }

    const float* objb = obj + (size_t)b * N_ * D_;

    for (int n0 = 0; n0 < N_; n0 += 32) {
#pragma unroll 8
        for (int i = 0; i < 32; i++) {
            sS[i][tx] = Rs[(size_t)(n0 + i) * R_ + r];
            sR[i][tx] = Rr[(size_t)(n0 + i) * R_ + r];
        }
        for (int i = tx; i < 32 * 32; i += 128)
            sO[i >> 5][i & 31] = objb[(size_t)n0 * D_ + i];
        __syncthreads();

#pragma unroll
        for (int i = 0; i < 32; i++) {
            const float s = sS[i][tx];
            const float t = sR[i][tx];
            const float4* o4 = reinterpret_cast<const float4*>(&sO[i][0]);
#pragma unroll
            for (int q = 0; q < 8; q++) {
                float4 o = o4[q];
                accS[4*q+0] += s * o.x; accD[4*q+0] += t * o.x;
                accS[4*q+1] += s * o.y; accD[4*q+1] += t * o.y;
                accS[4*q+2] += s * o.z; accD[4*q+2] += t * o.z;
                accS[4*q+3] += s * o.w; accD[4*q+3] += t * o.w;
            }
        }
        __syncthreads();
    }

    float* out = node + ((size_t)b * R_ + r) * 64;
#pragma unroll
    for (int d = 0; d < 32; d++) { out[d] = accS[d]; out[32 + d] = accD[d]; }
}

// ---------------------------------------------------------------------------
// Generic tiled GEMM: C[m,n] = act( sum_k A[m,k]*W[k,n] + bias[n] )
// Row-major with explicit leading dims + batch strides (batch = blockIdx.z).
// ---------------------------------------------------------------------------
template<int BM, int BN, int BK, int TM, int TN, bool RELU>
__global__ __launch_bounds__((BM / TM) * (BN / TN))
void gemm_br(const float* __restrict__ A, const float* __restrict__ W,
             const float* __restrict__ bias, float* __restrict__ C,
             int M, int Nn, int K, int lda, int ldb, int ldc,
             size_t sA, size_t sB, size_t sC)
{
    constexpr int THREADS = (BM / TM) * (BN / TN);
    __shared__ float As[BK][BM + 4];
    __shared__ float Bs[BK][BN];

    const int bz = blockIdx.z;
    A += sA * bz; W += sB * bz; C += sC * bz;

    const int tid  = threadIdx.x;
    const int tcol = tid % (BN / TN);
    const int trow = tid / (BN / TN);
    const int m0 = blockIdx.y * BM;
    const int n0 = blockIdx.x * BN;

    float acc[TM][TN];
#pragma unroll
    for (int i = 0; i < TM; i++)
#pragma unroll
        for (int j = 0; j < TN; j++) acc[i][j] = 0.f;

    for (int k0 = 0; k0 < K; k0 += BK) {
        // A tile: BM x BK, stored transposed
#pragma unroll
        for (int idx = tid; idx < BM * BK; idx += THREADS) {
            int m = idx / BK, k = idx % BK;
            float v = 0.f;
            if (m0 + m < M && k0 + k < K) v = A[(size_t)(m0 + m) * lda + k0 + k];
            As[k][m] = v;
        }
        // B tile: BK x BN
#pragma unroll
        for (int idx = tid; idx < BK * BN; idx += THREADS) {
            int k = idx / BN, n = idx % BN;
            float v = 0.f;
            if (k0 + k < K && n0 + n < Nn) v = W[(size_t)(k0 + k) * ldb + n0 + n];
            Bs[k][n] = v;
        }
        __syncthreads();

#pragma unroll
        for (int k = 0; k < BK; k++) {
            float a[TM], b[TN];
#pragma unroll
            for (int i = 0; i < TM; i++) a[i] = As[k][trow * TM + i];
#pragma unroll
            for (int j = 0; j < TN; j++) b[j] = Bs[k][tcol * TN + j];
#pragma unroll
            for (int i = 0; i < TM; i++)
#pragma unroll
                for (int j = 0; j < TN; j++)
                    acc[i][j] += a[i] * b[j];
        }
        __syncthreads();
    }

#pragma unroll
    for (int i = 0; i < TM; i++) {
        int m = m0 + trow * TM + i;
        if (m >= M) continue;
#pragma unroll
        for (int j = 0; j < TN; j++) {
            int n = n0 + tcol * TN + j;
            if (n >= Nn) continue;
            float v = acc[i][j];
            if (bias) v += bias[n];
            if (RELU) v = fmaxf(v, 0.f);
            C[(size_t)m * ldc + n] = v;
        }
    }
}

// ---------------------------------------------------------------------------
// Concat: upd[b*N+n, 0:32] = obj ; [32:96] = agg
// ---------------------------------------------------------------------------
__global__ void concat_kernel(const float* __restrict__ obj,
                              const float* __restrict__ agg,
                              float* __restrict__ upd)
{
    int i = blockIdx.x * 256 + threadIdx.x;
    if (i >= B_ * N_ * 96) return;
    int j  = i % 96;
    int bn = i / 96;
    upd[i] = (j < 32) ? obj[(size_t)bn * 32 + j] : agg[(size_t)bn * 64 + (j - 32)];
}

// ---------------------------------------------------------------------------
// Host-side launch helpers
// ---------------------------------------------------------------------------
template<int BM, int BN, int BK, int TM, int TN, bool RELU>
static void run_gemm(const float* A, const float* W, const float* bias, float* C,
                     int M, int Nn, int K, int lda, int ldb, int ldc,
                     size_t sA, size_t sB, size_t sC, int batch)
{
    dim3 grid((Nn + BN - 1) / BN, (M + BM - 1) / BM, batch);
    gemm_br<BM, BN, BK, TM, TN, RELU>
        <<<grid, (BM / TM) * (BN / TN)>>>(A, W, bias, C, M, Nn, K,
                                          lda, ldb, ldc, sA, sB, sC);
}

extern "C" void kernel_launch(void* const* d_in, const int* in_sizes, int n_in,
                              void* d_out, int out_size)
{
    const float* obj = (const float*)d_in[0];
    const float* Rs  = (const float*)d_in[1];
    const float* Rr  = (const float*)d_in[2];
    const float* rw1 = (const float*)d_in[3];  const float* rb1 = (const float*)d_in[4];
    const float* rw2 = (const float*)d_in[5];  const float* rb2 = (const float*)d_in[6];
    const float* rw3 = (const float*)d_in[7];  const float* rb3 = (const float*)d_in[8];
    const float* rw4 = (const float*)d_in[9];  const float* rb4 = (const float*)d_in[10];
    const float* ow1 = (const float*)d_in[11]; const float* ob1 = (const float*)d_in[12];
    const float* ow2 = (const float*)d_in[13]; const float* ob2 = (const float*)d_in[14];
    float* out = (float*)d_out;

    float *node, *h1, *h2, *edge, *agg, *upd, *hn;
    cudaGetSymbolAddress((void**)&node, g_node);
    cudaGetSymbolAddress((void**)&h1,   g_h1);
    cudaGetSymbolAddress((void**)&h2,   g_h2);
    cudaGetSymbolAddress((void**)&edge, g_edge);
    cudaGetSymbolAddress((void**)&agg,  g_agg);
    cudaGetSymbolAddress((void**)&upd,  g_upd);
    cudaGetSymbolAddress((void**)&hn,   g_hn);

    const int MR = B_ * R_;   // 131072 edge rows
    const int MN = B_ * N_;   // 8192  node rows

    // 1) gather: node_obj [B*R, 64]
    gather_kernel<<<dim3(R_ / 128, B_), 128>>>(obj, Rs, Rr, node);

    // 2) edge MLP
    run_gemm<128,128,16,8,8,true >(node, rw1, rb1, h1,  MR, H_,  64, 64, H_,  H_, 0,0,0, 1);
    run_gemm<128,128,16,8,8,true >(h1,   rw2, rb2, h2,  MR, H_, H_, H_, H_,  H_, 0,0,0, 1);
    run_gemm<128, 64,16,8,4,true >(h2,   rw3, rb3, node,MR, E_, H_, H_, E_,  E_, 0,0,0, 1); // h3 -> reuse g_node
    run_gemm<128, 64,16,8,4,true >(node, rw4, rb4, edge,MR, E_,  64, 64, E_,  E_, 0,0,0, 1);

    // 3) scatter-aggregate: agg[b] = Rr[N,R] @ edge[b][R,64]   (batched over b)
    run_gemm< 64, 64,16,4,4,false>(Rr, edge, nullptr, agg,
                                   N_, E_, R_, R_, E_, E_,
                                   0, (size_t)R_ * E_, (size_t)N_ * E_, B_);

    // 4) node MLP
    concat_kernel<<<(B_ * N_ * 96 + 255) / 256, 256>>>(obj, agg, upd);
    run_gemm<128,128,16,8,8,true >(upd, ow1, ob1, hn,  MN, H_,  96, 96, H_,  H_, 0,0,0, 1);
    run_gemm<128, 32,16,8,4,false>(hn,  ow2, ob2, out, MN, D_, H_, H_, D_,  D_, 0,0,0, 1);
}

// round 11
// speedup vs baseline: 2.7179x; 2.7179x over previous
#include <cuda_runtime.h>
#include <cuda_bf16.h>
#include <cstdint>
#include <cstddef>

#define B_  8
#define N_  1024
#define R_  16384
#define MR_ (B_*R_)
#define MN_ (B_*N_)
#define KSL 16

typedef __nv_bfloat16 bf16;

// ------------------------- scratch (device globals) -------------------------
__device__ bf16 g_RsT_h[(size_t)R_*N_],  g_RsT_l[(size_t)R_*N_];
__device__ bf16 g_RrT_h[(size_t)R_*N_],  g_RrT_l[(size_t)R_*N_];
__device__ bf16 g_Rr_h [(size_t)N_*R_],  g_Rr_l [(size_t)N_*R_];
__device__ bf16 g_oT_h [(size_t)256*N_], g_oT_l [(size_t)256*N_];
__device__ bf16 g_nd_h [(size_t)MR_*64], g_nd_l [(size_t)MR_*64];
__device__ bf16 g_h1_h [(size_t)MR_*512],g_h1_l [(size_t)MR_*512];
__device__ bf16 g_h2_h [(size_t)MR_*512],g_h2_l [(size_t)MR_*512];
__device__ bf16 g_eT_h [(size_t)512*R_], g_eT_l [(size_t)512*R_];
__device__ float g_part[(size_t)KSL*N_*512];
__device__ bf16 g_up_h [(size_t)MN_*128],g_up_l [(size_t)MN_*128];
__device__ bf16 g_hn_h [(size_t)MN_*512],g_hn_l [(size_t)MN_*512];
__device__ bf16 g_w1_h[512*64],  g_w1_l[512*64];
__device__ bf16 g_w2_h[512*512], g_w2_l[512*512];
__device__ bf16 g_w3_h[64*512],  g_w3_l[64*512];
__device__ bf16 g_w4_h[64*64],   g_w4_l[64*64];
__device__ bf16 g_v1_h[512*128], g_v1_l[512*128];
__device__ bf16 g_v2_h[32*512],  g_v2_l[32*512];

// ------------------------------- helpers ------------------------------------
__device__ __forceinline__ uint32_t smem_u32(const void* p){
    uint32_t a; asm("{ .reg .u64 t; cvta.to.shared.u64 t, %1; cvt.u32.u64 %0, t; }":"=r"(a):"l"(p)); return a;
}
__device__ __forceinline__ uint32_t swz(uint32_t off){ return off ^ ((off>>3)&0x70); }

__device__ __forceinline__ void ldm_x4(uint32_t* r,uint32_t a){
    asm volatile("ldmatrix.sync.aligned.m8n8.x4.shared.b16 {%0,%1,%2,%3},[%4];"
        :"=r"(r[0]),"=r"(r[1]),"=r"(r[2]),"=r"(r[3]):"r"(a));
}
__device__ __forceinline__ void ldm_x2(uint32_t* r,uint32_t a){
    asm volatile("ldmatrix.sync.aligned.m8n8.x2.shared.b16 {%0,%1},[%2];"
        :"=r"(r[0]),"=r"(r[1]):"r"(a));
}
__device__ __forceinline__ void mma_bf16(float* d,const uint32_t* a,const uint32_t* b){
    asm volatile("mma.sync.aligned.m16n8k16.row.col.f32.bf16.bf16.f32 "
        "{%0,%1,%2,%3},{%4,%5,%6,%7},{%8,%9},{%0,%1,%2,%3};"
        : "+f"(d[0]),"+f"(d[1]),"+f"(d[2]),"+f"(d[3])
        : "r"(a[0]),"r"(a[1]),"r"(a[2]),"r"(a[3]),"r"(b[0]),"r"(b[1]));
}

// --------------------------- HMMA split-bf16 GEMM ---------------------------
// D[M,N] = act(A[M,K] @ B[N,K]^T + bias). 128-row M tiles, NT-col N tiles,
// K chunks of 64 bf16 staged in swizzled SMEM (A planes @0/16384, B @32768..).
// MODE: 0 split planes out (ldc); 1 fp32 out (ldc); 2 transposed edgeT out;
//       3 gather node out (ldc = col base 0/32).
#define SBOF 32768
template<int NT,int MODE,bool RELU>
__global__ __launch_bounds__(256)
void hm_gemm(const bf16* __restrict__ Ah,const bf16* __restrict__ Al,int lda,
             const bf16* __restrict__ Bh,const bf16* __restrict__ Bl,int ldb,
             const float* __restrict__ bias,void* C0v,void* C1v,int ldc,
             size_t cZ,int stages,int kZ)
{
    extern __shared__ char smem[];
    const uint32_t sb = smem_u32(smem);
    const int tid=threadIdx.x, w=tid>>5, lane=tid&31;
    const int z=blockIdx.z, m0=blockIdx.y*128, n0=blockIdx.x*NT;
    const int kbase=z*kZ;
    constexpr int BPL = NT*128;
    constexpr int WARPS_M = (NT==128)?2:4;
    constexpr int WARPS_N = 8/WARPS_M;
    constexpr int WM = 128/WARPS_M;
    constexpr int WN = NT/WARPS_N;
    constexpr int MT = WM/16, NF = WN/8;
    const int wr = w % WARPS_M, wc = w / WARPS_M;

    float* Cf=nullptr; bf16* Ch=nullptr; bf16* Cl=nullptr;
    if(MODE==1) Cf=(float*)C0v + (size_t)z*cZ;
    else { Ch=(bf16*)C0v; Cl=(bf16*)C1v; }

    float acc[MT][NF][4];
#pragma unroll
    for(int i=0;i<MT;i++)
#pragma unroll
        for(int j=0;j<NF;j++)
#pragma unroll
            for(int q=0;q<4;q++) acc[i][j][q]=0.f;

    for(int s=0;s<stages;s++){
        const int kk=kbase+s*64;
        // ---- stage A (128x64 bf16, 2 planes) ----
#pragma unroll
        for(int pl=0;pl<2;pl++){
            const bf16* src = pl?Al:Ah;
            const int dofs = pl*16384;
#pragma unroll
            for(int it=0;it<4;it++){
                int idx=tid+it*256, row=idx>>3, c=idx&7;
                uint4 v=*reinterpret_cast<const uint4*>(src+(size_t)(m0+row)*lda+kk+c*8);
                *reinterpret_cast<uint4*>(smem+dofs+swz(row*128+c*16))=v;
            }
        }
        // ---- stage B (NTx64 bf16, 2 planes) ----
#pragma unroll
        for(int pl=0;pl<2;pl++){
            const bf16* src = pl?Bl:Bh;
            const int dofs = SBOF + pl*BPL;
#pragma unroll
            for(int it=0;it<NT/32;it++){
                int idx=tid+it*256, row=idx>>3, c=idx&7;
                uint4 v=*reinterpret_cast<const uint4*>(src+(size_t)(n0+row)*ldb+kk+c*8);
                *reinterpret_cast<uint4*>(smem+dofs+swz(row*128+c*16))=v;
            }
        }
        __syncthreads();

        // ---- compute: 4 k-steps of 16 ----
#pragma unroll
        for(int k16=0;k16<4;k16++){
            uint32_t bh[NF][2], bl[NF][2];
#pragma unroll
            for(int nf=0;nf<NF;nf++){
                int row = wc*WN + nf*8 + (lane&7);
                int colb = k16*32 + ((lane>>3)&1)*16;
                uint32_t off = swz((uint32_t)(row*128+colb));
                ldm_x2(bh[nf], sb + SBOF + off);
                ldm_x2(bl[nf], sb + SBOF + BPL + off);
            }
            uint32_t ar[MT][4];
#pragma unroll
            for(int mt=0;mt<MT;mt++){
                int row = wr*WM + mt*16 + (lane&15);
                int colb = k16*32 + (lane>>4)*16;
                ldm_x4(ar[mt], sb + swz((uint32_t)(row*128+colb)));
            }
#pragma unroll
            for(int mt=0;mt<MT;mt++)
#pragma unroll
                for(int nf=0;nf<NF;nf++){
                    mma_bf16(acc[mt][nf], ar[mt], bh[nf]);
                    mma_bf16(acc[mt][nf], ar[mt], bl[nf]);
                }
#pragma unroll
            for(int mt=0;mt<MT;mt++){
                int row = wr*WM + mt*16 + (lane&15);
                int colb = k16*32 + (lane>>4)*16;
                ldm_x4(ar[mt], sb + 16384 + swz((uint32_t)(row*128+colb)));
            }
#pragma unroll
            for(int mt=0;mt<MT;mt++)
#pragma unroll
                for(int nf=0;nf<NF;nf++)
                    mma_bf16(acc[mt][nf], ar[mt], bh[nf]);
        }
        __syncthreads();
    }

    // ------------------------------- epilogue -------------------------------
    if(MODE==2){
        // stage fp32 tile in smem, then write transposed edgeT rows
        float* fbuf = reinterpret_cast<float*>(smem);
#pragma unroll
        for(int mt=0;mt<MT;mt++)
#pragma unroll
            for(int nf=0;nf<NF;nf++){
                int ln = wc*WN + nf*8 + 2*(lane&3);
                float b0=0.f,b1=0.f;
                if(bias){ b0=bias[n0+ln]; b1=bias[n0+ln+1]; }
#pragma unroll
                for(int rr=0;rr<2;rr++){
                    int lm = wr*WM + mt*16 + (lane>>2) + rr*8;
                    float v0=acc[mt][nf][rr*2+0]+b0;
                    float v1=acc[mt][nf][rr*2+1]+b1;
                    if(RELU){ v0=fmaxf(v0,0.f); v1=fmaxf(v1,0.f); }
                    fbuf[lm*(NT+1)+ln]=v0;
                    fbuf[lm*(NT+1)+ln+1]=v1;
                }
            }
        __syncthreads();
        const int bb = m0>>14, r0g = m0&(R_-1);
        for(int idx=tid; idx<NT*128; idx+=256){
            int nn=idx>>7, mm=idx&127;
            float v=fbuf[mm*(NT+1)+nn];
            bf16 hi=__float2bfloat16(v);
            size_t o=((size_t)bb*64+(n0+nn))*(size_t)R_ + r0g+mm;
            Ch[o]=hi; Cl[o]=__float2bfloat16(v-__bfloat162float(hi));
        }
        return;
    }

#pragma unroll
    for(int mt=0;mt<MT;mt++)
#pragma unroll
        for(int nf=0;nf<NF;nf++){
            int c0 = n0 + wc*WN + nf*8 + 2*(lane&3);
            float b0=0.f,b1=0.f;
            if(bias){ b0=bias[c0]; b1=bias[c0+1]; }
#pragma unroll
            for(int rr=0;rr<2;rr++){
                int gm = m0 + wr*WM + mt*16 + (lane>>2) + rr*8;
                float v0=acc[mt][nf][rr*2+0]+b0;
                float v1=acc[mt][nf][rr*2+1]+b1;
                if(RELU){ v0=fmaxf(v0,0.f); v1=fmaxf(v1,0.f); }
                if(MODE==1){
                    *reinterpret_cast<float2*>(Cf+(size_t)gm*ldc+c0)=make_float2(v0,v1);
                } else {
                    size_t o;
                    if(MODE==0) o=(size_t)gm*ldc+c0;
                    else        o=((size_t)(c0>>5)*R_+gm)*64 + ldc + (c0&31);
                    __nv_bfloat162 hi2=__floats2bfloat162_rn(v0,v1);
                    float h0=__bfloat162float(__low2bfloat16(hi2));
                    float h1=__bfloat162float(__high2bfloat16(hi2));
                    __nv_bfloat162 lo2=__floats2bfloat162_rn(v0-h0,v1-h1);
                    *reinterpret_cast<__nv_bfloat162*>(Ch+o)=hi2;
                    *reinterpret_cast<__nv_bfloat162*>(Cl+o)=lo2;
                }
            }
        }
}

// ------------------------------- prep kernels -------------------------------
__global__ void tsplit(const float* __restrict__ in,bf16* __restrict__ oh,bf16* __restrict__ ol,
                       int P,int ldin,int ldout,size_t inB,size_t outB)
{
    __shared__ float t[32][33];
    in+=(size_t)blockIdx.z*inB; oh+=(size_t)blockIdx.z*outB; ol+=(size_t)blockIdx.z*outB;
    int p0=blockIdx.x*32, q0=blockIdx.y*32, tx=threadIdx.x, ty=threadIdx.y;
#pragma unroll
    for(int i=0;i<4;i++){
        int p=p0+ty+i*8; float v=0.f;
        if(p<P) v=in[(size_t)p*ldin+q0+tx];
        t[ty+i*8][tx]=v;
    }
    __syncthreads();
#pragma unroll
    for(int i=0;i<4;i++){
        int q=q0+ty+i*8, pp=p0+tx;
        float v=t[tx][ty+i*8];
        bf16 hi=__float2bfloat16(v);
        oh[(size_t)q*ldout+pp]=hi;
        ol[(size_t)q*ldout+pp]=__float2bfloat16(v-__bfloat162float(hi));
    }
}
__global__ void psplit(const float* __restrict__ in,bf16* __restrict__ oh,bf16* __restrict__ ol,int n){
    int i=blockIdx.x*256+threadIdx.x; if(i>=n) return;
    float v=in[i]; bf16 hi=__float2bfloat16(v);
    oh[i]=hi; ol[i]=__float2bfloat16(v-__bfloat162float(hi));
}
__global__ void reduce_concat(const float* __restrict__ obj,const float* __restrict__ part,
                              bf16* __restrict__ uh,bf16* __restrict__ ul)
{
    int i=blockIdx.x*256+threadIdx.x; if(i>=MN_*128) return;
    int col=i&127, bn=i>>7;
    float v=0.f;
    if(col<32) v=obj[(size_t)bn*32+col];
    else if(col<96){
        int e=col-32, b=bn>>10, n=bn&1023;
        size_t base=(size_t)n*512+b*64+e;
#pragma unroll
        for(int ks=0;ks<KSL;ks++) v+=part[(size_t)ks*N_*512+base];
    }
    bf16 hi=__float2bfloat16(v);
    uh[i]=hi; ul[i]=__float2bfloat16(v-__bfloat162float(hi));
}

// ---------------------------------- host ------------------------------------
static inline int smB(int nt){ return SBOF + nt*256; }

extern "C" void kernel_launch(void* const* d_in,const int* in_sizes,int n_in,
                              void* d_out,int out_size)
{
    const float* obj=(const float*)d_in[0];
    const float* Rs =(const float*)d_in[1];
    const float* Rr =(const float*)d_in[2];
    const float* rw1=(const float*)d_in[3];  const float* rb1=(const float*)d_in[4];
    const float* rw2=(const float*)d_in[5];  const float* rb2=(const float*)d_in[6];
    const float* rw3=(const float*)d_in[7];  const float* rb3=(const float*)d_in[8];
    const float* rw4=(const float*)d_in[9];  const float* rb4=(const float*)d_in[10];
    const float* ow1=(const float*)d_in[11]; const float* ob1=(const float*)d_in[12];
    const float* ow2=(const float*)d_in[13]; const float* ob2=(const float*)d_in[14];
    float* out=(float*)d_out;

    bf16 *RsTh,*RsTl,*RrTh,*RrTl,*Rrh,*Rrl,*oTh,*oTl,*ndh,*ndl,*h1h,*h1l,*h2h,*h2l;
    bf16 *eTh,*eTl,*uph,*upl,*hnh,*hnl,*w1h,*w1l,*w2h,*w2l,*w3h,*w3l,*w4h,*w4l,*v1h,*v1l,*v2h,*v2l;
    float* part;
    cudaGetSymbolAddress((void**)&RsTh,g_RsT_h); cudaGetSymbolAddress((void**)&RsTl,g_RsT_l);
    cudaGetSymbolAddress((void**)&RrTh,g_RrT_h); cudaGetSymbolAddress((void**)&RrTl,g_RrT_l);
    cudaGetSymbolAddress((void**)&Rrh,g_Rr_h);   cudaGetSymbolAddress((void**)&Rrl,g_Rr_l);
    cudaGetSymbolAddress((void**)&oTh,g_oT_h);   cudaGetSymbolAddress((void**)&oTl,g_oT_l);
    cudaGetSymbolAddress((void**)&ndh,g_nd_h);   cudaGetSymbolAddress((void**)&ndl,g_nd_l);
    cudaGetSymbolAddress((void**)&h1h,g_h1_h);   cudaGetSymbolAddress((void**)&h1l,g_h1_l);
    cudaGetSymbolAddress((void**)&h2h,g_h2_h);   cudaGetSymbolAddress((void**)&h2l,g_h2_l);
    cudaGetSymbolAddress((void**)&eTh,g_eT_h);   cudaGetSymbolAddress((void**)&eTl,g_eT_l);
    cudaGetSymbolAddress((void**)&part,g_part);
    cudaGetSymbolAddress((void**)&uph,g_up_h);   cudaGetSymbolAddress((void**)&upl,g_up_l);
    cudaGetSymbolAddress((void**)&hnh,g_hn_h);   cudaGetSymbolAddress((void**)&hnl,g_hn_l);
    cudaGetSymbolAddress((void**)&w1h,g_w1_h);   cudaGetSymbolAddress((void**)&w1l,g_w1_l);
    cudaGetSymbolAddress((void**)&w2h,g_w2_h);   cudaGetSymbolAddress((void**)&w2l,g_w2_l);
    cudaGetSymbolAddress((void**)&w3h,g_w3_h);   cudaGetSymbolAddress((void**)&w3l,g_w3_l);
    cudaGetSymbolAddress((void**)&w4h,g_w4_h);   cudaGetSymbolAddress((void**)&w4l,g_w4_l);
    cudaGetSymbolAddress((void**)&v1h,g_v1_h);   cudaGetSymbolAddress((void**)&v1l,g_v1_l);
    cudaGetSymbolAddress((void**)&v2h,g_v2_h);   cudaGetSymbolAddress((void**)&v2l,g_v2_l);

    cudaFuncSetAttribute(hm_gemm<128,3,false>,cudaFuncAttributeMaxDynamicSharedMemorySize,smB(128));
    cudaFuncSetAttribute(hm_gemm<128,0,true >,cudaFuncAttributeMaxDynamicSharedMemorySize,smB(128));
    cudaFuncSetAttribute(hm_gemm< 64,0,true >,cudaFuncAttributeMaxDynamicSharedMemorySize,smB(64));
    cudaFuncSetAttribute(hm_gemm< 64,2,true >,cudaFuncAttributeMaxDynamicSharedMemorySize,smB(64));
    cudaFuncSetAttribute(hm_gemm<128,1,false>,cudaFuncAttributeMaxDynamicSharedMemorySize,smB(128));
    cudaFuncSetAttribute(hm_gemm< 32,1,false>,cudaFuncAttributeMaxDynamicSharedMemorySize,smB(32));

    dim3 tb(32,8);
    // prep: transposes + splits
    tsplit<<<dim3(32,512,1),tb>>>(Rs, RsTh,RsTl, 1024,R_,1024, 0,0);
    tsplit<<<dim3(32,512,1),tb>>>(Rr, RrTh,RrTl, 1024,R_,1024, 0,0);
    psplit<<<(N_*R_+255)/256,256>>>(Rr, Rrh,Rrl, N_*R_);
    tsplit<<<dim3(32,1,8),tb>>>(obj, oTh,oTl, 1024,32,1024, (size_t)N_*32,(size_t)32*N_);
    tsplit<<<dim3(2,16,1),tb>>>(rw1, w1h,w1l, 64,512,64, 0,0);
    tsplit<<<dim3(16,16,1),tb>>>(rw2, w2h,w2l, 512,512,512, 0,0);
    tsplit<<<dim3(16,2,1),tb>>>(rw3, w3h,w3l, 512,64,512, 0,0);
    tsplit<<<dim3(2,2,1),tb>>>(rw4, w4h,w4l, 64,64,64, 0,0);
    tsplit<<<dim3(4,16,1),tb>>>(ow1, v1h,v1l, 96,512,128, 0,0);
    tsplit<<<dim3(16,1,1),tb>>>(ow2, v2h,v2l, 512,32,512, 0,0);

    // gather: node[b*R+r, 0:32]=src, [32:64]=dst
    hm_gemm<128,3,false><<<dim3(2,128,1),256,smB(128)>>>(RsTh,RsTl,1024, oTh,oTl,1024, nullptr, ndh,ndl, 0, 0, 16,0);
    hm_gemm<128,3,false><<<dim3(2,128,1),256,smB(128)>>>(RrTh,RrTl,1024, oTh,oTl,1024, nullptr, ndh,ndl, 32,0, 16,0);
    // edge MLP
    hm_gemm<128,0,true ><<<dim3(4,1024,1),256,smB(128)>>>(ndh,ndl,64,  w1h,w1l,64,  rb1, h1h,h1l, 512,0, 1,0);
    hm_gemm<128,0,true ><<<dim3(4,1024,1),256,smB(128)>>>(h1h,h1l,512, w2h,w2l,512, rb2, h2h,h2l, 512,0, 8,0);
    hm_gemm< 64,0,true ><<<dim3(1,1024,1),256,smB(64)>>>(h2h,h2l,512, w3h,w3l,512, rb3, ndh,ndl, 64,0, 8,0);
    hm_gemm< 64,2,true ><<<dim3(1,1024,1),256,smB(64)>>>(ndh,ndl,64,  w4h,w4l,64,  rb4, eTh,eTl, 0,0, 1,0);
    // scatter-aggregate (split-K=16, fp32 partials), then reduce+concat
    hm_gemm<128,1,false><<<dim3(4,8,KSL),256,smB(128)>>>(Rrh,Rrl,R_, eTh,eTl,R_, nullptr, part,nullptr, 512,(size_t)N_*512, 16,1024);
    reduce_concat<<<(MN_*128+255)/256,256>>>(obj, part, uph,upl);
    // node MLP
    hm_gemm<128,0,true ><<<dim3(4,64,1),256,smB(128)>>>(uph,upl,128, v1h,v1l,128, ob1, hnh,hnl, 512,0, 2,0);
    hm_gemm< 32,1,false><<<dim3(1,64,1),256,smB(32)>>>(hnh,hnl,512, v2h,v2l,512, ob2, out,nullptr, 32,0, 8,0);
}

// round 12
// speedup vs baseline: 4.4890x; 1.6516x over previous
#include <cuda_runtime.h>
#include <cuda_bf16.h>
#include <cstdint>
#include <cstddef>

#define B_  8
#define N_  1024
#define R_  16384
#define MR_ (B_*R_)
#define MN_ (B_*N_)
#define KSL 16

typedef __nv_bfloat16 bf16;

// ------------------------- scratch (device globals) -------------------------
__device__ bf16 g_RsT_h[(size_t)R_*N_],  g_RsT_l[(size_t)R_*N_];
__device__ bf16 g_RrT_h[(size_t)R_*N_],  g_RrT_l[(size_t)R_*N_];
__device__ bf16 g_Rr_h [(size_t)N_*R_],  g_Rr_l [(size_t)N_*R_];
__device__ bf16 g_oT_h [(size_t)256*N_], g_oT_l [(size_t)256*N_];
__device__ bf16 g_nd_h [(size_t)MR_*64], g_nd_l [(size_t)MR_*64];
__device__ bf16 g_h1_h [(size_t)MR_*512],g_h1_l [(size_t)MR_*512];
__device__ bf16 g_h2_h [(size_t)MR_*512],g_h2_l [(size_t)MR_*512];
__device__ bf16 g_eT_h [(size_t)512*R_], g_eT_l [(size_t)512*R_];
__device__ float g_part[(size_t)KSL*N_*512];
__device__ bf16 g_up_h [(size_t)MN_*128],g_up_l [(size_t)MN_*128];
__device__ bf16 g_hn_h [(size_t)MN_*512],g_hn_l [(size_t)MN_*512];
__device__ bf16 g_w1_h[512*64],  g_w1_l[512*64];
__device__ bf16 g_w2_h[512*512], g_w2_l[512*512];
__device__ bf16 g_w3_h[64*512],  g_w3_l[64*512];
__device__ bf16 g_w4_h[64*64],   g_w4_l[64*64];
__device__ bf16 g_v1_h[512*128], g_v1_l[512*128];
__device__ bf16 g_v2_h[32*512],  g_v2_l[32*512];

// ------------------------------- helpers ------------------------------------
__device__ __forceinline__ uint32_t smem_u32(const void* p){
    uint32_t a; asm("{ .reg .u64 t; cvta.to.shared.u64 t, %1; cvt.u32.u64 %0, t; }":"=r"(a):"l"(p)); return a;
}
__device__ __forceinline__ uint32_t swz(uint32_t off){ return off ^ ((off>>3)&0x70); }

__device__ __forceinline__ void cp16(uint32_t dst, const void* src){
    asm volatile("cp.async.cg.shared.global [%0], [%1], 16;" :: "r"(dst), "l"(src) : "memory");
}
__device__ __forceinline__ void cp_commit(){ asm volatile("cp.async.commit_group;" ::: "memory"); }

__device__ __forceinline__ void ldm_x4(uint32_t* r,uint32_t a){
    asm volatile("ldmatrix.sync.aligned.m8n8.x4.shared.b16 {%0,%1,%2,%3},[%4];"
        :"=r"(r[0]),"=r"(r[1]),"=r"(r[2]),"=r"(r[3]):"r"(a));
}
__device__ __forceinline__ void ldm_x2(uint32_t* r,uint32_t a){
    asm volatile("ldmatrix.sync.aligned.m8n8.x2.shared.b16 {%0,%1},[%2];"
        :"=r"(r[0]),"=r"(r[1]):"r"(a));
}
__device__ __forceinline__ void mma_bf16(float* d,const uint32_t* a,const uint32_t* b){
    asm volatile("mma.sync.aligned.m16n8k16.row.col.f32.bf16.bf16.f32 "
        "{%0,%1,%2,%3},{%4,%5,%6,%7},{%8,%9},{%0,%1,%2,%3};"
        : "+f"(d[0]),"+f"(d[1]),"+f"(d[2]),"+f"(d[3])
        : "r"(a[0]),"r"(a[1]),"r"(a[2]),"r"(a[3]),"r"(b[0]),"r"(b[1]));
}

// --------------------------- HMMA split-bf16 GEMM ---------------------------
// D[M,N] = act(A[M,K] @ B[N,K]^T + bias). 128-row M tiles, NT-col N tiles,
// K chunks of 64 bf16, cp.async double-buffered SMEM pipeline.
// Buffer layout (per stage p at p*BUF): A planes @0/16384, B planes @32768.
// MODE: 0 split planes out (ldc); 1 fp32 out (ldc); 2 transposed edgeT out;
//       3 gather node out (ldc = col base 0/32).
template<int NT,int MODE,bool RELU>
__global__ __launch_bounds__(256)
void hm_gemm(const bf16* __restrict__ Ah,const bf16* __restrict__ Al,int lda,
             const bf16* __restrict__ Bh,const bf16* __restrict__ Bl,int ldb,
             const float* __restrict__ bias,void* C0v,void* C1v,int ldc,
             size_t cZ,int stages,int kZ)
{
    extern __shared__ char smem[];
    const uint32_t sb = smem_u32(smem);
    const int tid=threadIdx.x, w=tid>>5, lane=tid&31;
    const int z=blockIdx.z, m0=blockIdx.y*128, n0=blockIdx.x*NT;
    const int kbase=z*kZ;
    constexpr int BPL = NT*128;             // bytes per B plane
    constexpr uint32_t BUF = 32768u + 2u*BPL;
    constexpr int WARPS_M = (NT==128)?2:4;
    constexpr int WARPS_N = 8/WARPS_M;
    constexpr int WM = 128/WARPS_M;
    constexpr int WN = NT/WARPS_N;
    constexpr int MT = WM/16, NF = WN/8;
    const int wr = w % WARPS_M, wc = w / WARPS_M;

    float* Cf=nullptr; bf16* Ch=nullptr; bf16* Cl=nullptr;
    if(MODE==1) Cf=(float*)C0v + (size_t)z*cZ;
    else { Ch=(bf16*)C0v; Cl=(bf16*)C1v; }

    float acc[MT][NF][4];
#pragma unroll
    for(int i=0;i<MT;i++)
#pragma unroll
        for(int j=0;j<NF;j++)
#pragma unroll
            for(int q=0;q<4;q++) acc[i][j][q]=0.f;

    // ---- async stage loader ----
    auto load_stage = [&](int s){
        const int kk = kbase + s*64;
        const uint32_t base = sb + (uint32_t)(s&1)*BUF;
#pragma unroll
        for(int pl=0;pl<2;pl++){
            const bf16* src = pl?Al:Ah;
            const uint32_t dofs = base + pl*16384;
#pragma unroll
            for(int it=0;it<4;it++){
                int idx=tid+it*256, row=idx>>3, c=idx&7;
                cp16(dofs+swz((uint32_t)(row*128+c*16)),
                     src+(size_t)(m0+row)*lda+kk+c*8);
            }
        }
#pragma unroll
        for(int pl=0;pl<2;pl++){
            const bf16* src = pl?Bl:Bh;
            const uint32_t dofs = base + 32768u + (uint32_t)pl*BPL;
#pragma unroll
            for(int it=0;it<NT/32;it++){
                int idx=tid+it*256, row=idx>>3, c=idx&7;
                cp16(dofs+swz((uint32_t)(row*128+c*16)),
                     src+(size_t)(n0+row)*ldb+kk+c*8);
            }
        }
        cp_commit();
    };

    load_stage(0);

    for(int s=0;s<stages;s++){
        if(s+1<stages){
            load_stage(s+1);
            asm volatile("cp.async.wait_group 1;" ::: "memory");
        } else {
            asm volatile("cp.async.wait_group 0;" ::: "memory");
        }
        __syncthreads();

        const uint32_t base = sb + (uint32_t)(s&1)*BUF;
        const uint32_t bbase = base + 32768u;
#pragma unroll
        for(int k16=0;k16<4;k16++){
            uint32_t bh[NF][2], bl[NF][2];
#pragma unroll
            for(int nf=0;nf<NF;nf++){
                int row = wc*WN + nf*8 + (lane&7);
                int colb = k16*32 + ((lane>>3)&1)*16;
                uint32_t off = swz((uint32_t)(row*128+colb));
                ldm_x2(bh[nf], bbase + off);
                ldm_x2(bl[nf], bbase + BPL + off);
            }
            uint32_t ar[MT][4];
#pragma unroll
            for(int mt=0;mt<MT;mt++){
                int row = wr*WM + mt*16 + (lane&15);
                int colb = k16*32 + (lane>>4)*16;
                ldm_x4(ar[mt], base + swz((uint32_t)(row*128+colb)));
            }
#pragma unroll
            for(int mt=0;mt<MT;mt++)
#pragma unroll
                for(int nf=0;nf<NF;nf++){
                    mma_bf16(acc[mt][nf], ar[mt], bh[nf]);
                    mma_bf16(acc[mt][nf], ar[mt], bl[nf]);
                }
#pragma unroll
            for(int mt=0;mt<MT;mt++){
                int row = wr*WM + mt*16 + (lane&15);
                int colb = k16*32 + (lane>>4)*16;
                ldm_x4(ar[mt], base + 16384u + swz((uint32_t)(row*128+colb)));
            }
#pragma unroll
            for(int mt=0;mt<MT;mt++)
#pragma unroll
                for(int nf=0;nf<NF;nf++)
                    mma_bf16(acc[mt][nf], ar[mt], bh[nf]);
        }
        __syncthreads();
    }

    // ------------------------------- epilogue -------------------------------
    if(MODE==2){
        float* fbuf = reinterpret_cast<float*>(smem);
#pragma unroll
        for(int mt=0;mt<MT;mt++)
#pragma unroll
            for(int nf=0;nf<NF;nf++){
                int ln = wc*WN + nf*8 + 2*(lane&3);
                float b0=0.f,b1=0.f;
                if(bias){ b0=bias[n0+ln]; b1=bias[n0+ln+1]; }
#pragma unroll
                for(int rr=0;rr<2;rr++){
                    int lm = wr*WM + mt*16 + (lane>>2) + rr*8;
                    float v0=acc[mt][nf][rr*2+0]+b0;
                    float v1=acc[mt][nf][rr*2+1]+b1;
                    if(RELU){ v0=fmaxf(v0,0.f); v1=fmaxf(v1,0.f); }
                    fbuf[lm*(NT+1)+ln]=v0;
                    fbuf[lm*(NT+1)+ln+1]=v1;
                }
            }
        __syncthreads();
        const int bb = m0>>14, r0g = m0&(R_-1);
        for(int idx=tid; idx<NT*128; idx+=256){
            int nn=idx>>7, mm=idx&127;
            float v=fbuf[mm*(NT+1)+nn];
            bf16 hi=__float2bfloat16(v);
            size_t o=((size_t)bb*64+(n0+nn))*(size_t)R_ + r0g+mm;
            Ch[o]=hi; Cl[o]=__float2bfloat16(v-__bfloat162float(hi));
        }
        return;
    }

#pragma unroll
    for(int mt=0;mt<MT;mt++)
#pragma unroll
        for(int nf=0;nf<NF;nf++){
            int c0 = n0 + wc*WN + nf*8 + 2*(lane&3);
            float b0=0.f,b1=0.f;
            if(bias){ b0=bias[c0]; b1=bias[c0+1]; }
#pragma unroll
            for(int rr=0;rr<2;rr++){
                int gm = m0 + wr*WM + mt*16 + (lane>>2) + rr*8;
                float v0=acc[mt][nf][rr*2+0]+b0;
                float v1=acc[mt][nf][rr*2+1]+b1;
                if(RELU){ v0=fmaxf(v0,0.f); v1=fmaxf(v1,0.f); }
                if(MODE==1){
                    *reinterpret_cast<float2*>(Cf+(size_t)gm*ldc+c0)=make_float2(v0,v1);
                } else {
                    size_t o;
                    if(MODE==0) o=(size_t)gm*ldc+c0;
                    else        o=((size_t)(c0>>5)*R_+gm)*64 + ldc + (c0&31);
                    __nv_bfloat162 hi2=__floats2bfloat162_rn(v0,v1);
                    float h0=__bfloat162float(__low2bfloat16(hi2));
                    float h1=__bfloat162float(__high2bfloat16(hi2));
                    __nv_bfloat162 lo2=__floats2bfloat162_rn(v0-h0,v1-h1);
                    *reinterpret_cast<__nv_bfloat162*>(Ch+o)=hi2;
                    *reinterpret_cast<__nv_bfloat162*>(Cl+o)=lo2;
                }
            }
        }
}

// ------------------------------- prep kernels -------------------------------
__global__ void tsplit(const float* __restrict__ in,bf16* __restrict__ oh,bf16* __restrict__ ol,
                       int P,int ldin,int ldout,size_t inB,size_t outB)
{
    __shared__ float t[32][33];
    in+=(size_t)blockIdx.z*inB; oh+=(size_t)blockIdx.z*outB; ol+=(size_t)blockIdx.z*outB;
    int p0=blockIdx.x*32, q0=blockIdx.y*32, tx=threadIdx.x, ty=threadIdx.y;
#pragma unroll
    for(int i=0;i<4;i++){
        int p=p0+ty+i*8; float v=0.f;
        if(p<P) v=in[(size_t)p*ldin+q0+tx];
        t[ty+i*8][tx]=v;
    }
    __syncthreads();
#pragma unroll
    for(int i=0;i<4;i++){
        int q=q0+ty+i*8, pp=p0+tx;
        float v=t[tx][ty+i*8];
        bf16 hi=__float2bfloat16(v);
        oh[(size_t)q*ldout+pp]=hi;
        ol[(size_t)q*ldout+pp]=__float2bfloat16(v-__bfloat162float(hi));
    }
}
__global__ void psplit(const float* __restrict__ in,bf16* __restrict__ oh,bf16* __restrict__ ol,int n){
    int i=blockIdx.x*256+threadIdx.x; if(i>=n) return;
    float v=in[i]; bf16 hi=__float2bfloat16(v);
    oh[i]=hi; ol[i]=__float2bfloat16(v-__bfloat162float(hi));
}
__global__ void reduce_concat(const float* __restrict__ obj,const float* __restrict__ part,
                              bf16* __restrict__ uh,bf16* __restrict__ ul)
{
    int i=blockIdx.x*256+threadIdx.x; if(i>=MN_*128) return;
    int col=i&127, bn=i>>7;
    float v=0.f;
    if(col<32) v=obj[(size_t)bn*32+col];
    else if(col<96){
        int e=col-32, b=bn>>10, n=bn&1023;
        size_t base=(size_t)n*512+b*64+e;
#pragma unroll
        for(int ks=0;ks<KSL;ks++) v+=part[(size_t)ks*N_*512+base];
    }
    bf16 hi=__float2bfloat16(v);
    uh[i]=hi; ul[i]=__float2bfloat16(v-__bfloat162float(hi));
}

// ---------------------------------- host ------------------------------------
static inline int smB(int nt){ return 2*(32768 + nt*256); }

extern "C" void kernel_launch(void* const* d_in,const int* in_sizes,int n_in,
                              void* d_out,int out_size)
{
    const float* obj=(const float*)d_in[0];
    const float* Rs =(const float*)d_in[1];
    const float* Rr =(const float*)d_in[2];
    const float* rw1=(const float*)d_in[3];  const float* rb1=(const float*)d_in[4];
    const float* rw2=(const float*)d_in[5];  const float* rb2=(const float*)d_in[6];
    const float* rw3=(const float*)d_in[7];  const float* rb3=(const float*)d_in[8];
    const float* rw4=(const float*)d_in[9];  const float* rb4=(const float*)d_in[10];
    const float* ow1=(const float*)d_in[11]; const float* ob1=(const float*)d_in[12];
    const float* ow2=(const float*)d_in[13]; const float* ob2=(const float*)d_in[14];
    float* out=(float*)d_out;

    bf16 *RsTh,*RsTl,*RrTh,*RrTl,*Rrh,*Rrl,*oTh,*oTl,*ndh,*ndl,*h1h,*h1l,*h2h,*h2l;
    bf16 *eTh,*eTl,*uph,*upl,*hnh,*hnl,*w1h,*w1l,*w2h,*w2l,*w3h,*w3l,*w4h,*w4l,*v1h,*v1l,*v2h,*v2l;
    float* part;
    cudaGetSymbolAddress((void**)&RsTh,g_RsT_h); cudaGetSymbolAddress((void**)&RsTl,g_RsT_l);
    cudaGetSymbolAddress((void**)&RrTh,g_RrT_h); cudaGetSymbolAddress((void**)&RrTl,g_RrT_l);
    cudaGetSymbolAddress((void**)&Rrh,g_Rr_h);   cudaGetSymbolAddress((void**)&Rrl,g_Rr_l);
    cudaGetSymbolAddress((void**)&oTh,g_oT_h);   cudaGetSymbolAddress((void**)&oTl,g_oT_l);
    cudaGetSymbolAddress((void**)&ndh,g_nd_h);   cudaGetSymbolAddress((void**)&ndl,g_nd_l);
    cudaGetSymbolAddress((void**)&h1h,g_h1_h);   cudaGetSymbolAddress((void**)&h1l,g_h1_l);
    cudaGetSymbolAddress((void**)&h2h,g_h2_h);   cudaGetSymbolAddress((void**)&h2l,g_h2_l);
    cudaGetSymbolAddress((void**)&eTh,g_eT_h);   cudaGetSymbolAddress((void**)&eTl,g_eT_l);
    cudaGetSymbolAddress((void**)&part,g_part);
    cudaGetSymbolAddress((void**)&uph,g_up_h);   cudaGetSymbolAddress((void**)&upl,g_up_l);
    cudaGetSymbolAddress((void**)&hnh,g_hn_h);   cudaGetSymbolAddress((void**)&hnl,g_hn_l);
    cudaGetSymbolAddress((void**)&w1h,g_w1_h);   cudaGetSymbolAddress((void**)&w1l,g_w1_l);
    cudaGetSymbolAddress((void**)&w2h,g_w2_h);   cudaGetSymbolAddress((void**)&w2l,g_w2_l);
    cudaGetSymbolAddress((void**)&w3h,g_w3_h);   cudaGetSymbolAddress((void**)&w3l,g_w3_l);
    cudaGetSymbolAddress((void**)&w4h,g_w4_h);   cudaGetSymbolAddress((void**)&w4l,g_w4_l);
    cudaGetSymbolAddress((void**)&v1h,g_v1_h);   cudaGetSymbolAddress((void**)&v1l,g_v1_l);
    cudaGetSymbolAddress((void**)&v2h,g_v2_h);   cudaGetSymbolAddress((void**)&v2l,g_v2_l);

    cudaFuncSetAttribute(hm_gemm<128,3,false>,cudaFuncAttributeMaxDynamicSharedMemorySize,smB(128));
    cudaFuncSetAttribute(hm_gemm<128,0,true >,cudaFuncAttributeMaxDynamicSharedMemorySize,smB(128));
    cudaFuncSetAttribute(hm_gemm< 64,0,true >,cudaFuncAttributeMaxDynamicSharedMemorySize,smB(64));
    cudaFuncSetAttribute(hm_gemm< 64,2,true >,cudaFuncAttributeMaxDynamicSharedMemorySize,smB(64));
    cudaFuncSetAttribute(hm_gemm<128,1,false>,cudaFuncAttributeMaxDynamicSharedMemorySize,smB(128));
    cudaFuncSetAttribute(hm_gemm< 32,1,false>,cudaFuncAttributeMaxDynamicSharedMemorySize,smB(32));

    dim3 tb(32,8);
    // prep: transposes + splits
    tsplit<<<dim3(32,512,1),tb>>>(Rs, RsTh,RsTl, 1024,R_,1024, 0,0);
    tsplit<<<dim3(32,512,1),tb>>>(Rr, RrTh,RrTl, 1024,R_,1024, 0,0);
    psplit<<<(N_*R_+255)/256,256>>>(Rr, Rrh,Rrl, N_*R_);
    tsplit<<<dim3(32,1,8),tb>>>(obj, oTh,oTl, 1024,32,1024, (size_t)N_*32,(size_t)32*N_);
    tsplit<<<dim3(2,16,1),tb>>>(rw1, w1h,w1l, 64,512,64, 0,0);
    tsplit<<<dim3(16,16,1),tb>>>(rw2, w2h,w2l, 512,512,512, 0,0);
    tsplit<<<dim3(16,2,1),tb>>>(rw3, w3h,w3l, 512,64,512, 0,0);
    tsplit<<<dim3(2,2,1),tb>>>(rw4, w4h,w4l, 64,64,64, 0,0);
    tsplit<<<dim3(4,16,1),tb>>>(ow1, v1h,v1l, 96,512,128, 0,0);
    tsplit<<<dim3(16,1,1),tb>>>(ow2, v2h,v2l, 512,32,512, 0,0);

    // gather: node[b*R+r, 0:32]=src, [32:64]=dst
    hm_gemm<128,3,false><<<dim3(2,128,1),256,smB(128)>>>(RsTh,RsTl,1024, oTh,oTl,1024, nullptr, ndh,ndl, 0, 0, 16,0);
    hm_gemm<128,3,false><<<dim3(2,128,1),256,smB(128)>>>(RrTh,RrTl,1024, oTh,oTl,1024, nullptr, ndh,ndl, 32,0, 16,0);
    // edge MLP
    hm_gemm<128,0,true ><<<dim3(4,1024,1),256,smB(128)>>>(ndh,ndl,64,  w1h,w1l,64,  rb1, h1h,h1l, 512,0, 1,0);
    hm_gemm<128,0,true ><<<dim3(4,1024,1),256,smB(128)>>>(h1h,h1l,512, w2h,w2l,512, rb2, h2h,h2l, 512,0, 8,0);
    hm_gemm< 64,0,true ><<<dim3(1,1024,1),256,smB(64)>>>(h2h,h2l,512, w3h,w3l,512, rb3, ndh,ndl, 64,0, 8,0);
    hm_gemm< 64,2,true ><<<dim3(1,1024,1),256,smB(64)>>>(ndh,ndl,64,  w4h,w4l,64,  rb4, eTh,eTl, 0,0, 1,0);
    // scatter-aggregate (split-K=16, fp32 partials), then reduce+concat
    hm_gemm<128,1,false><<<dim3(4,8,KSL),256,smB(128)>>>(Rrh,Rrl,R_, eTh,eTl,R_, nullptr, part,nullptr, 512,(size_t)N_*512, 16,1024);
    reduce_concat<<<(MN_*128+255)/256,256>>>(obj, part, uph,upl);
    // node MLP
    hm_gemm<128,0,true ><<<dim3(4,64,1),256,smB(128)>>>(uph,upl,128, v1h,v1l,128, ob1, hnh,hnl, 512,0, 2,0);
    hm_gemm< 32,1,false><<<dim3(1,64,1),256,smB(32)>>>(hnh,hnl,512, v2h,v2l,512, ob2, out,nullptr, 32,0, 8,0);
}

// round 13
// speedup vs baseline: 6.3743x; 1.4200x over previous
#include <cuda_runtime.h>
#include <cuda_fp16.h>
#include <cstdint>
#include <cstddef>

#define B_  8
#define N_  1024
#define R_  16384
#define MR_ (B_*R_)
#define MN_ (B_*N_)
#define KSL 16

typedef __half h16;

// ------------------------- scratch (device globals) -------------------------
// A-side tensors: hi plane only. B-side tensors: hi+lo planes.
__device__ h16 g_RsT_h[(size_t)R_*N_];
__device__ h16 g_RrT_h[(size_t)R_*N_];
__device__ h16 g_Rr_h [(size_t)N_*R_];
__device__ h16 g_oT_h [(size_t)256*N_], g_oT_l [(size_t)256*N_];
__device__ h16 g_nd_h [(size_t)MR_*64];
__device__ h16 g_h1_h [(size_t)MR_*512];
__device__ h16 g_h2_h [(size_t)MR_*512];
__device__ h16 g_eT_h [(size_t)512*R_], g_eT_l [(size_t)512*R_];
__device__ float g_part[(size_t)KSL*N_*512];
__device__ h16 g_up_h [(size_t)MN_*128];
__device__ h16 g_hn_h [(size_t)MN_*512];
__device__ h16 g_w1_h[512*64],  g_w1_l[512*64];
__device__ h16 g_w2_h[512*512], g_w2_l[512*512];
__device__ h16 g_w3_h[64*512],  g_w3_l[64*512];
__device__ h16 g_w4_h[64*64],   g_w4_l[64*64];
__device__ h16 g_v1_h[512*128], g_v1_l[512*128];
__device__ h16 g_v2_h[32*512],  g_v2_l[32*512];

// ------------------------------- helpers ------------------------------------
__device__ __forceinline__ uint32_t smem_u32(const void* p){
    uint32_t a; asm("{ .reg .u64 t; cvta.to.shared.u64 t, %1; cvt.u32.u64 %0, t; }":"=r"(a):"l"(p)); return a;
}
__device__ __forceinline__ uint32_t swz(uint32_t off){ return off ^ ((off>>3)&0x70); }

__device__ __forceinline__ void cp16(uint32_t dst, const void* src){
    asm volatile("cp.async.cg.shared.global [%0], [%1], 16;" :: "r"(dst), "l"(src) : "memory");
}
__device__ __forceinline__ void cp_commit(){ asm volatile("cp.async.commit_group;" ::: "memory"); }

__device__ __forceinline__ void ldm_x4(uint32_t* r,uint32_t a){
    asm volatile("ldmatrix.sync.aligned.m8n8.x4.shared.b16 {%0,%1,%2,%3},[%4];"
        :"=r"(r[0]),"=r"(r[1]),"=r"(r[2]),"=r"(r[3]):"r"(a));
}
__device__ __forceinline__ void ldm_x2(uint32_t* r,uint32_t a){
    asm volatile("ldmatrix.sync.aligned.m8n8.x2.shared.b16 {%0,%1},[%2];"
        :"=r"(r[0]),"=r"(r[1]):"r"(a));
}
__device__ __forceinline__ void mma_f16(float* d,const uint32_t* a,const uint32_t* b){
    asm volatile("mma.sync.aligned.m16n8k16.row.col.f32.f16.f16.f32 "
        "{%0,%1,%2,%3},{%4,%5,%6,%7},{%8,%9},{%0,%1,%2,%3};"
        : "+f"(d[0]),"+f"(d[1]),"+f"(d[2]),"+f"(d[3])
        : "r"(a[0]),"r"(a[1]),"r"(a[2]),"r"(a[3]),"r"(b[0]),"r"(b[1]));
}

// --------------------------- HMMA fp16-split GEMM ---------------------------
// D[M,N] = act(A[M,K] @ B[N,K]^T + bias).  A = hi plane only (fp16 quantized);
// B = hi + lo planes (2 MMA passes: A*Bh + A*Bl).
// 128-row M tiles, NT-col N tiles, K chunks of 64, cp.async double buffer.
// Buffer p at p*BUF: A @0 (16KB), B hi @16384, B lo @16384+BPL.
// MODE: 0 fp16 hi out (ldc); 1 fp32 out (ldc); 2 transposed edgeT out (hi+lo);
//       3 gather node out (ldc = col base 0/32).
template<int NT,int MODE,bool RELU>
__global__ __launch_bounds__(256)
void hm_gemm(const h16* __restrict__ Ah,int lda,
             const h16* __restrict__ Bh,const h16* __restrict__ Bl,int ldb,
             const float* __restrict__ bias,void* C0v,void* C1v,int ldc,
             size_t cZ,int stages,int kZ)
{
    extern __shared__ char smem[];
    const uint32_t sb = smem_u32(smem);
    const int tid=threadIdx.x, w=tid>>5, lane=tid&31;
    const int z=blockIdx.z, m0=blockIdx.y*128, n0=blockIdx.x*NT;
    const int kbase=z*kZ;
    constexpr int BPL = NT*128;                 // bytes per B plane
    constexpr uint32_t BUF = 16384u + 2u*BPL;
    constexpr int WARPS_M = (NT==128)?2:4;
    constexpr int WARPS_N = 8/WARPS_M;
    constexpr int WM = 128/WARPS_M;
    constexpr int WN = NT/WARPS_N;
    constexpr int MT = WM/16, NF = WN/8;
    const int wr = w % WARPS_M, wc = w / WARPS_M;

    float* Cf=nullptr; h16* Ch=nullptr; h16* Cl=nullptr;
    if(MODE==1) Cf=(float*)C0v + (size_t)z*cZ;
    else { Ch=(h16*)C0v; Cl=(h16*)C1v; }

    float acc[MT][NF][4];
#pragma unroll
    for(int i=0;i<MT;i++)
#pragma unroll
        for(int j=0;j<NF;j++)
#pragma unroll
            for(int q=0;q<4;q++) acc[i][j][q]=0.f;

    auto load_stage = [&](int s){
        const int kk = kbase + s*64;
        const uint32_t base = sb + (uint32_t)(s&1)*BUF;
        // A tile: 128 x 64 fp16 (hi plane)
#pragma unroll
        for(int it=0;it<4;it++){
            int idx=tid+it*256, row=idx>>3, c=idx&7;
            cp16(base+swz((uint32_t)(row*128+c*16)),
                 Ah+(size_t)(m0+row)*lda+kk+c*8);
        }
        // B tiles: NT x 64 fp16, 2 planes
#pragma unroll
        for(int pl=0;pl<2;pl++){
            const h16* src = pl?Bl:Bh;
            const uint32_t dofs = base + 16384u + (uint32_t)pl*BPL;
#pragma unroll
            for(int it=0;it<NT/32;it++){
                int idx=tid+it*256, row=idx>>3, c=idx&7;
                cp16(dofs+swz((uint32_t)(row*128+c*16)),
                     src+(size_t)(n0+row)*ldb+kk+c*8);
            }
        }
        cp_commit();
    };

    load_stage(0);

    for(int s=0;s<stages;s++){
        if(s+1<stages){
            load_stage(s+1);
            asm volatile("cp.async.wait_group 1;" ::: "memory");
        } else {
            asm volatile("cp.async.wait_group 0;" ::: "memory");
        }
        __syncthreads();

        const uint32_t base = sb + (uint32_t)(s&1)*BUF;
        const uint32_t bbase = base + 16384u;
#pragma unroll
        for(int k16=0;k16<4;k16++){
            uint32_t bh[NF][2], bl[NF][2];
#pragma unroll
            for(int nf=0;nf<NF;nf++){
                int row = wc*WN + nf*8 + (lane&7);
                int colb = k16*32 + ((lane>>3)&1)*16;
                uint32_t off = swz((uint32_t)(row*128+colb));
                ldm_x2(bh[nf], bbase + off);
                ldm_x2(bl[nf], bbase + BPL + off);
            }
            uint32_t ar[MT][4];
#pragma unroll
            for(int mt=0;mt<MT;mt++){
                int row = wr*WM + mt*16 + (lane&15);
                int colb = k16*32 + (lane>>4)*16;
                ldm_x4(ar[mt], base + swz((uint32_t)(row*128+colb)));
            }
#pragma unroll
            for(int mt=0;mt<MT;mt++)
#pragma unroll
                for(int nf=0;nf<NF;nf++){
                    mma_f16(acc[mt][nf], ar[mt], bh[nf]);
                    mma_f16(acc[mt][nf], ar[mt], bl[nf]);
                }
        }
        __syncthreads();
    }

    // ------------------------------- epilogue -------------------------------
    if(MODE==2){
        float* fbuf = reinterpret_cast<float*>(smem);
#pragma unroll
        for(int mt=0;mt<MT;mt++)
#pragma unroll
            for(int nf=0;nf<NF;nf++){
                int ln = wc*WN + nf*8 + 2*(lane&3);
                float b0=0.f,b1=0.f;
                if(bias){ b0=bias[n0+ln]; b1=bias[n0+ln+1]; }
#pragma unroll
                for(int rr=0;rr<2;rr++){
                    int lm = wr*WM + mt*16 + (lane>>2) + rr*8;
                    float v0=acc[mt][nf][rr*2+0]+b0;
                    float v1=acc[mt][nf][rr*2+1]+b1;
                    if(RELU){ v0=fmaxf(v0,0.f); v1=fmaxf(v1,0.f); }
                    fbuf[lm*(NT+1)+ln]=v0;
                    fbuf[lm*(NT+1)+ln+1]=v1;
                }
            }
        __syncthreads();
        const int bb = m0>>14, r0g = m0&(R_-1);
        for(int idx=tid; idx<NT*128; idx+=256){
            int nn=idx>>7, mm=idx&127;
            float v=fbuf[mm*(NT+1)+nn];
            h16 hi=__float2half_rn(v);
            size_t o=((size_t)bb*64+(n0+nn))*(size_t)R_ + r0g+mm;
            Ch[o]=hi; Cl[o]=__float2half_rn(v-__half2float(hi));
        }
        return;
    }

#pragma unroll
    for(int mt=0;mt<MT;mt++)
#pragma unroll
        for(int nf=0;nf<NF;nf++){
            int c0 = n0 + wc*WN + nf*8 + 2*(lane&3);
            float b0=0.f,b1=0.f;
            if(bias){ b0=bias[c0]; b1=bias[c0+1]; }
#pragma unroll
            for(int rr=0;rr<2;rr++){
                int gm = m0 + wr*WM + mt*16 + (lane>>2) + rr*8;
                float v0=acc[mt][nf][rr*2+0]+b0;
                float v1=acc[mt][nf][rr*2+1]+b1;
                if(RELU){ v0=fmaxf(v0,0.f); v1=fmaxf(v1,0.f); }
                if(MODE==1){
                    *reinterpret_cast<float2*>(Cf+(size_t)gm*ldc+c0)=make_float2(v0,v1);
                } else {
                    size_t o;
                    if(MODE==0) o=(size_t)gm*ldc+c0;
                    else        o=((size_t)(c0>>5)*R_+gm)*64 + ldc + (c0&31);
                    *reinterpret_cast<__half2*>(Ch+o)=__floats2half2_rn(v0,v1);
                }
            }
        }
}

// ------------------------------- prep kernels -------------------------------
// transpose+split: fp32 [P,Q](ldin) -> fp16 hi [Q,ldout] (+lo if ol!=null)
__global__ void tsplit(const float* __restrict__ in,h16* __restrict__ oh,h16* __restrict__ ol,
                       int P,int ldin,int ldout,size_t inB,size_t outB)
{
    __shared__ float t[32][33];
    in+=(size_t)blockIdx.z*inB; oh+=(size_t)blockIdx.z*outB;
    if(ol) ol+=(size_t)blockIdx.z*outB;
    int p0=blockIdx.x*32, q0=blockIdx.y*32, tx=threadIdx.x, ty=threadIdx.y;
#pragma unroll
    for(int i=0;i<4;i++){
        int p=p0+ty+i*8; float v=0.f;
        if(p<P) v=in[(size_t)p*ldin+q0+tx];
        t[ty+i*8][tx]=v;
    }
    __syncthreads();
#pragma unroll
    for(int i=0;i<4;i++){
        int q=q0+ty+i*8, pp=p0+tx;
        float v=t[tx][ty+i*8];
        h16 hi=__float2half_rn(v);
        oh[(size_t)q*ldout+pp]=hi;
        if(ol) ol[(size_t)q*ldout+pp]=__float2half_rn(v-__half2float(hi));
    }
}
__global__ void psplit(const float* __restrict__ in,h16* __restrict__ oh,int n){
    int i=blockIdx.x*256+threadIdx.x; if(i>=n) return;
    oh[i]=__float2half_rn(in[i]);
}
// reduce split-K partials + concat -> up hi plane [MN,128] (cols 96..127 = 0)
__global__ void reduce_concat(const float* __restrict__ obj,const float* __restrict__ part,
                              h16* __restrict__ uh)
{
    int i=blockIdx.x*256+threadIdx.x; if(i>=MN_*128) return;
    int col=i&127, bn=i>>7;
    float v=0.f;
    if(col<32) v=obj[(size_t)bn*32+col];
    else if(col<96){
        int e=col-32, b=bn>>10, n=bn&1023;
        size_t base=(size_t)n*512+b*64+e;
#pragma unroll
        for(int ks=0;ks<KSL;ks++) v+=part[(size_t)ks*N_*512+base];
    }
    uh[i]=__float2half_rn(v);
}

// ---------------------------------- host ------------------------------------
static inline int smB(int nt){ return 2*(16384 + nt*256); }

extern "C" void kernel_launch(void* const* d_in,const int* in_sizes,int n_in,
                              void* d_out,int out_size)
{
    const float* obj=(const float*)d_in[0];
    const float* Rs =(const float*)d_in[1];
    const float* Rr =(const float*)d_in[2];
    const float* rw1=(const float*)d_in[3];  const float* rb1=(const float*)d_in[4];
    const float* rw2=(const float*)d_in[5];  const float* rb2=(const float*)d_in[6];
    const float* rw3=(const float*)d_in[7];  const float* rb3=(const float*)d_in[8];
    const float* rw4=(const float*)d_in[9];  const float* rb4=(const float*)d_in[10];
    const float* ow1=(const float*)d_in[11]; const float* ob1=(const float*)d_in[12];
    const float* ow2=(const float*)d_in[13]; const float* ob2=(const float*)d_in[14];
    float* out=(float*)d_out;

    h16 *RsTh,*RrTh,*Rrh,*oTh,*oTl,*ndh,*h1h,*h2h,*eTh,*eTl,*uph,*hnh;
    h16 *w1h,*w1l,*w2h,*w2l,*w3h,*w3l,*w4h,*w4l,*v1h,*v1l,*v2h,*v2l;
    float* part;
    cudaGetSymbolAddress((void**)&RsTh,g_RsT_h);
    cudaGetSymbolAddress((void**)&RrTh,g_RrT_h);
    cudaGetSymbolAddress((void**)&Rrh,g_Rr_h);
    cudaGetSymbolAddress((void**)&oTh,g_oT_h);   cudaGetSymbolAddress((void**)&oTl,g_oT_l);
    cudaGetSymbolAddress((void**)&ndh,g_nd_h);
    cudaGetSymbolAddress((void**)&h1h,g_h1_h);
    cudaGetSymbolAddress((void**)&h2h,g_h2_h);
    cudaGetSymbolAddress((void**)&eTh,g_eT_h);   cudaGetSymbolAddress((void**)&eTl,g_eT_l);
    cudaGetSymbolAddress((void**)&part,g_part);
    cudaGetSymbolAddress((void**)&uph,g_up_h);
    cudaGetSymbolAddress((void**)&hnh,g_hn_h);
    cudaGetSymbolAddress((void**)&w1h,g_w1_h);   cudaGetSymbolAddress((void**)&w1l,g_w1_l);
    cudaGetSymbolAddress((void**)&w2h,g_w2_h);   cudaGetSymbolAddress((void**)&w2l,g_w2_l);
    cudaGetSymbolAddress((void**)&w3h,g_w3_h);   cudaGetSymbolAddress((void**)&w3l,g_w3_l);
    cudaGetSymbolAddress((void**)&w4h,g_w4_h);   cudaGetSymbolAddress((void**)&w4l,g_w4_l);
    cudaGetSymbolAddress((void**)&v1h,g_v1_h);   cudaGetSymbolAddress((void**)&v1l,g_v1_l);
    cudaGetSymbolAddress((void**)&v2h,g_v2_h);   cudaGetSymbolAddress((void**)&v2l,g_v2_l);

    cudaFuncSetAttribute(hm_gemm<128,3,false>,cudaFuncAttributeMaxDynamicSharedMemorySize,smB(128));
    cudaFuncSetAttribute(hm_gemm<128,0,true >,cudaFuncAttributeMaxDynamicSharedMemorySize,smB(128));
    cudaFuncSetAttribute(hm_gemm< 64,0,true >,cudaFuncAttributeMaxDynamicSharedMemorySize,smB(64));
    cudaFuncSetAttribute(hm_gemm< 64,2,true >,cudaFuncAttributeMaxDynamicSharedMemorySize,smB(64));
    cudaFuncSetAttribute(hm_gemm<128,1,false>,cudaFuncAttributeMaxDynamicSharedMemorySize,smB(128));
    cudaFuncSetAttribute(hm_gemm< 32,1,false>,cudaFuncAttributeMaxDynamicSharedMemorySize,smB(32));

    dim3 tb(32,8);
    // prep: transposes + splits (lo plane only where tensor is a B operand)
    tsplit<<<dim3(32,512,1),tb>>>(Rs, RsTh,nullptr, 1024,R_,1024, 0,0);
    tsplit<<<dim3(32,512,1),tb>>>(Rr, RrTh,nullptr, 1024,R_,1024, 0,0);
    psplit<<<(N_*R_+255)/256,256>>>(Rr, Rrh, N_*R_);
    tsplit<<<dim3(32,1,8),tb>>>(obj, oTh,oTl, 1024,32,1024, (size_t)N_*32,(size_t)32*N_);
    tsplit<<<dim3(2,16,1),tb>>>(rw1, w1h,w1l, 64,512,64, 0,0);
    tsplit<<<dim3(16,16,1),tb>>>(rw2, w2h,w2l, 512,512,512, 0,0);
    tsplit<<<dim3(16,2,1),tb>>>(rw3, w3h,w3l, 512,64,512, 0,0);
    tsplit<<<dim3(2,2,1),tb>>>(rw4, w4h,w4l, 64,64,64, 0,0);
    tsplit<<<dim3(4,16,1),tb>>>(ow1, v1h,v1l, 96,512,128, 0,0);
    tsplit<<<dim3(16,1,1),tb>>>(ow2, v2h,v2l, 512,32,512, 0,0);

    // gather: node[b*R+r, 0:32]=src(Rs), [32:64]=dst(Rr)
    hm_gemm<128,3,false><<<dim3(2,128,1),256,smB(128)>>>(RsTh,1024, oTh,oTl,1024, nullptr, ndh,nullptr, 0, 0, 16,0);
    hm_gemm<128,3,false><<<dim3(2,128,1),256,smB(128)>>>(RrTh,1024, oTh,oTl,1024, nullptr, ndh,nullptr, 32,0, 16,0);
    // edge MLP
    hm_gemm<128,0,true ><<<dim3(4,1024,1),256,smB(128)>>>(ndh,64,  w1h,w1l,64,  rb1, h1h,nullptr, 512,0, 1,0);
    hm_gemm<128,0,true ><<<dim3(4,1024,1),256,smB(128)>>>(h1h,512, w2h,w2l,512, rb2, h2h,nullptr, 512,0, 8,0);
    hm_gemm< 64,0,true ><<<dim3(1,1024,1),256,smB(64)>>>(h2h,512, w3h,w3l,512, rb3, ndh,nullptr, 64,0, 8,0);
    hm_gemm< 64,2,true ><<<dim3(1,1024,1),256,smB(64)>>>(ndh,64,  w4h,w4l,64,  rb4, eTh,eTl, 0,0, 1,0);
    // scatter-aggregate (split-K=16, fp32 partials), then reduce+concat
    hm_gemm<128,1,false><<<dim3(4,8,KSL),256,smB(128)>>>(Rrh,R_, eTh,eTl,R_, nullptr, part,nullptr, 512,(size_t)N_*512, 16,1024);
    reduce_concat<<<(MN_*128+255)/256,256>>>(obj, part, uph);
    // node MLP
    hm_gemm<128,0,true ><<<dim3(4,64,1),256,smB(128)>>>(uph,128, v1h,v1l,128, ob1, hnh,nullptr, 512,0, 2,0);
    hm_gemm< 32,1,false><<<dim3(1,64,1),256,smB(32)>>>(hnh,512, v2h,v2l,512, ob2, out,nullptr, 32,0, 8,0);
}